// round 15
// baseline (speedup 1.0000x reference)
#include <cuda_runtime.h>
#include <cuda_bf16.h>
#include <cstdint>
#include <math.h>

// ---- packed f32x2 helpers ------------------------------------------------
typedef unsigned long long u64;
__device__ __forceinline__ u64 pk2(float lo, float hi) {
    u64 r; asm("mov.b64 %0, {%1, %2};" : "=l"(r) : "f"(lo), "f"(hi)); return r;
}
__device__ __forceinline__ float2 up2(u64 v) {
    float2 r; asm("mov.b64 {%0, %1}, %2;" : "=f"(r.x), "=f"(r.y) : "l"(v)); return r;
}
__device__ __forceinline__ void fma2(u64& d, u64 a, u64 b) {
    asm("fma.rn.f32x2 %0, %1, %2, %0;" : "+l"(d) : "l"(a), "l"(b));
}
__device__ __forceinline__ u64 lds2(const float2* p) { return *(const u64*)p; }
__device__ __forceinline__ int swz(int m) { return m + (m >> 3); }

__device__ __forceinline__ uint32_t smem_u32(const void* p) {
    uint32_t a;
    asm("{ .reg .u64 t; cvta.to.shared.u64 t, %1; cvt.u32.u64 %0, t; }"
        : "=r"(a) : "l"(p));
    return a;
}
#define SMEM_SWZ128(o) ((o) ^ (((o) >> 3) & 0x70))

// ---- warp-level mma.sync helpers (base ISA, compiles on compute_103) -----
__device__ __forceinline__ void ldmx4(uint32_t& a0, uint32_t& a1,
                                      uint32_t& a2, uint32_t& a3, uint32_t addr) {
    asm volatile("ldmatrix.sync.aligned.m8n8.x4.shared.b16 {%0,%1,%2,%3}, [%4];"
                 : "=r"(a0), "=r"(a1), "=r"(a2), "=r"(a3) : "r"(addr));
}
__device__ __forceinline__ void ldmx2(uint32_t& b0, uint32_t& b1, uint32_t addr) {
    asm volatile("ldmatrix.sync.aligned.m8n8.x2.shared.b16 {%0,%1}, [%2];"
                 : "=r"(b0), "=r"(b1) : "r"(addr));
}
__device__ __forceinline__ void mma16816(float* c, uint32_t a0, uint32_t a1,
                                         uint32_t a2, uint32_t a3,
                                         uint32_t b0, uint32_t b1) {
    asm volatile(
        "mma.sync.aligned.m16n8k16.row.col.f32.bf16.bf16.f32 "
        "{%0,%1,%2,%3}, {%4,%5,%6,%7}, {%8,%9}, {%0,%1,%2,%3};"
        : "+f"(c[0]), "+f"(c[1]), "+f"(c[2]), "+f"(c[3])
        : "r"(a0), "r"(a1), "r"(a2), "r"(a3), "r"(b0), "r"(b1));
}

// Intermediate activations (static device globals).
__device__ float g_a2[32*50*16*16];
__device__ float g_a2c[16*50*16*16];
__device__ float g_a3[16*50*32*64];
__device__ float g_a4[16*50*64*256];
// bf16 hi/lo transposed+halo activations for MMA k2: [h32][w'70][b32][cin64]
__device__ __nv_bfloat16 g_a1t_hi[32*70*32*64];
__device__ __nv_bfloat16 g_a1t_lo[32*70*32*64];
// prepped weights: [tap21][hi/lo 2][co64][cin64]
__device__ __nv_bfloat16 g_w2t[21*2*64*64];

__global__ void knop() {}

// ---------------------------------------------------------------------------
// K2W: weight prep: w2[50,50,3,7] fp32 -> g_w2t bf16 hi/lo, zero-padded.
// ---------------------------------------------------------------------------
__global__ void k2w(const float* __restrict__ w2) {
    const int tap = blockIdx.x;          // 0..20
    const int p = tap / 7, q = tap % 7;
    for (int idx = threadIdx.x; idx < 4096; idx += 256) {
        int co = idx >> 6, cin = idx & 63;
        float v = 0.f;
        if (co < 50 && cin < 50)
            v = w2[((co*50 + cin)*3 + p)*7 + q];
        __nv_bfloat16 hi = __float2bfloat16(v);
        __nv_bfloat16 lo = __float2bfloat16(v - __bfloat162float(hi));
        g_w2t[(tap*2 + 0)*4096 + idx] = hi;
        g_w2t[(tap*2 + 1)*4096 + idx] = lo;
    }
}

// ---------------------------------------------------------------------------
// K1: circular conv1 (1->50, 3x7 on 64x256) + maxpool(2,4) + relu.
// Epilogue writes bf16 hi/lo transposed+halo activations for MMA k2.
// ---------------------------------------------------------------------------
__global__ void k1(const float* __restrict__ x, const float* __restrict__ w1,
                   const float* __restrict__ b1) {
    __shared__ float sx[10][256];
    __shared__ float sw[50*21];
    const int b = blockIdx.y, strip = blockIdx.x;
    const int tid = threadIdx.x;
    const float* xb = x + b*64*256;
    for (int idx = tid; idx < 10*256; idx += 256) {
        int l = idx >> 8, col = idx & 255;
        int row = (strip*8 - 2 + l) & 63;
        sx[l][col] = xb[row*256 + col];
    }
    for (int idx = tid; idx < 1050; idx += 256) sw[idx] = w1[idx];
    __syncthreads();

    const int prl = tid >> 6;
    const int pw  = tid & 63;
    float xv[4][10];
    #pragma unroll
    for (int rl = 0; rl < 4; rl++)
        #pragma unroll
        for (int j = 0; j < 10; j++)
            xv[rl][j] = sx[prl*2 + rl][(pw*4 - 6 + j) & 255];

    const int pr = strip*4 + prl;
    const int base1 = ((pr*70 + (pw + 6))*32 + b)*64;
    const int base2 = (pw >= 58) ? ((pr*70 + (pw - 58))*32 + b)*64 : -1;
    for (int co = 0; co < 50; co++) {
        float acc[8];
        #pragma unroll
        for (int i = 0; i < 8; i++) acc[i] = 0.f;
        #pragma unroll
        for (int p = 0; p < 3; p++)
            #pragma unroll
            for (int q = 0; q < 7; q++) {
                float wv = sw[co*21 + p*7 + q];
                #pragma unroll
                for (int dr = 0; dr < 2; dr++)
                    #pragma unroll
                    for (int dc = 0; dc < 4; dc++)
                        acc[dr*4+dc] += wv * xv[dr + 2 - p][dc + 6 - q];
            }
        float m = acc[0];
        #pragma unroll
        for (int i = 1; i < 8; i++) m = fmaxf(m, acc[i]);
        float val = fmaxf(m + b1[co], 0.f);
        __nv_bfloat16 hi = __float2bfloat16(val);
        __nv_bfloat16 lo = __float2bfloat16(val - __bfloat162float(hi));
        g_a1t_hi[base1 + co] = hi;
        g_a1t_lo[base1 + co] = lo;
        if (base2 >= 0) { g_a1t_hi[base2 + co] = hi; g_a1t_lo[base2 + co] = lo; }
    }
    __nv_bfloat16 z = __float2bfloat16(0.f);
    for (int co = 50; co < 64; co++) {
        g_a1t_hi[base1 + co] = z; g_a1t_lo[base1 + co] = z;
        if (base2 >= 0) { g_a1t_hi[base2 + co] = z; g_a1t_lo[base2 + co] = z; }
    }
}

// ---------------------------------------------------------------------------
// K2M: conv2 + maxpool + relu via warp-level mma.sync bf16 shift-GEMM
// (hi/lo 3-pass). Block = (pooled row r, batch pair bp), 256 threads
// (8 warps). Warp w owns M-rows [16w,16w+16) of M=128 = (conv col, bsel).
// N=64 co, K=64 cin. acc[2 dh][8 ntiles][4] f32 in regs.
// smem arena: A tiles 4x16KB (dh x hi/lo) @0, W 2x8KB @65536.
// Epilogue reuses arena for D[2][128][64] staging, then pool 2x4+bias+relu.
// ---------------------------------------------------------------------------
extern __shared__ __align__(1024) char k2m_arena[];
__global__ void __launch_bounds__(256, 2)
k2m(const float* __restrict__ b2) {
    const int r = blockIdx.x, bp = blockIdx.y;
    const int tid = threadIdx.x;
    const int wid = tid >> 5, lid = tid & 31;
    char* arena = k2m_arena;

    float acc[2][8][4];
    #pragma unroll
    for (int dh = 0; dh < 2; dh++)
        #pragma unroll
        for (int nt = 0; nt < 8; nt++)
            #pragma unroll
            for (int i = 0; i < 4; i++) acc[dh][nt][i] = 0.f;

    const uint32_t abase0 = smem_u32(arena);
    const uint32_t wbase0 = smem_u32(arena + 65536);
    const int mrow0 = wid*16;

    for (int tap = 0; tap < 21; tap++) {
        const int p = tap / 7, q = tap % 7;
        __syncthreads();      // previous iteration's ldmatrix done (warp-sync)
        // stage 4 A tiles (dh x hi/lo), 128 rows x 128B each, SW128
        for (int it = tid; it < 4096; it += 256) {
            int t = it >> 10;                 // tile: dh*2 + hl
            int rc = it & 1023;
            int row = rc >> 3, ch = rc & 7;
            int dh = t >> 1, hl = t & 1;
            int w = row >> 1, bsel = row & 1;
            int hin = (2*r + dh - p) & 31;
            const __nv_bfloat16* src = (hl ? g_a1t_lo : g_a1t_hi)
                + (((hin*70 + (w - q + 6))*32 + (bp*2 + bsel)) << 6) + (ch << 3);
            uint4 v = *(const uint4*)src;
            *(uint4*)(arena + t*16384 + SMEM_SWZ128((row << 7) + (ch << 4))) = v;
        }
        // stage W hi/lo tiles, 64 rows x 128B each
        for (int it = tid; it < 1024; it += 256) {
            int hl = it >> 9;
            int rc = it & 511;
            int row = rc >> 3, ch = rc & 7;
            const __nv_bfloat16* src = g_w2t + (tap*2 + hl)*4096 + (row << 6) + (ch << 3);
            uint4 v = *(const uint4*)src;
            *(uint4*)(arena + 65536 + hl*8192 + SMEM_SWZ128((row << 7) + (ch << 4))) = v;
        }
        __syncthreads();

        #pragma unroll
        for (int pass = 0; pass < 3; pass++) {
            const int ahl = (pass == 2) ? 1 : 0;
            const int bhl = (pass == 1) ? 1 : 0;
            #pragma unroll
            for (int kk = 0; kk < 4; kk++) {
                // B fragments: 8 n-tiles x 2 regs (W[n][k] row-major = col B)
                uint32_t bf[8][2];
                {
                    int rowb = (lid & 7);
                    int kc = kk*16 + ((lid & 8) ? 8 : 0);
                    #pragma unroll
                    for (int nt = 0; nt < 8; nt++) {
                        uint32_t addr = wbase0 + bhl*8192 +
                            SMEM_SWZ128((((nt << 3) + rowb) << 7) + (kc << 1));
                        ldmx2(bf[nt][0], bf[nt][1], addr);
                    }
                }
                #pragma unroll
                for (int dh = 0; dh < 2; dh++) {
                    uint32_t a0, a1, a2, a3;
                    int rowa = mrow0 + (lid & 15);
                    int kca = kk*16 + ((lid >> 4) << 3);
                    uint32_t addr = abase0 + (dh*2 + ahl)*16384 +
                        SMEM_SWZ128((rowa << 7) + (kca << 1));
                    ldmx4(a0, a1, a2, a3, addr);
                    #pragma unroll
                    for (int nt = 0; nt < 8; nt++)
                        mma16816(acc[dh][nt], a0, a1, a2, a3,
                                 bf[nt][0], bf[nt][1]);
                }
            }
        }
    }
    __syncthreads();   // tiles dead; arena reused for D staging

    float* Dsm = (float*)arena;          // [2][128][64]
    {
        int r0 = mrow0 + (lid >> 2);
        int c0 = (lid & 3)*2;
        #pragma unroll
        for (int dh = 0; dh < 2; dh++)
            #pragma unroll
            for (int nt = 0; nt < 8; nt++) {
                int c = nt*8 + c0;
                Dsm[(dh*128 + r0)*64 + c]     = acc[dh][nt][0];
                Dsm[(dh*128 + r0)*64 + c + 1] = acc[dh][nt][1];
                Dsm[(dh*128 + r0 + 8)*64 + c]     = acc[dh][nt][2];
                Dsm[(dh*128 + r0 + 8)*64 + c + 1] = acc[dh][nt][3];
            }
    }
    __syncthreads();

    // maxpool(2h x 4w) + bias + relu -> g_a2[b, co, r, pw]
    for (int idx = tid; idx < 1600; idx += 256) {
        int co = idx % 50;
        int rest = idx / 50;
        int pw = rest & 15, bsel = rest >> 4;
        float mx = -1e30f;
        #pragma unroll
        for (int dh = 0; dh < 2; dh++)
            #pragma unroll
            for (int dw = 0; dw < 4; dw++) {
                int m = (pw*4 + dw)*2 + bsel;
                mx = fmaxf(mx, Dsm[(dh*128 + m)*64 + co]);
            }
        float val = fmaxf(mx + b2[co], 0.f);
        g_a2[(((bp*2 + bsel)*50 + co)*16 + r)*16 + pw] = val;
    }
}

// ---------------------------------------------------------------------------
// K3: combine: out[b] = a2[2b] + mean_{hw}(a2[2b+1]).  grid 800 = 16*50.
// ---------------------------------------------------------------------------
__global__ void k3() {
    const int bc = blockIdx.x;
    const int b = bc / 50, c = bc % 50;
    const int t = threadIdx.x;
    const float* ev = g_a2 + ((2*b)*50 + c)*256;
    const float* od = g_a2 + ((2*b + 1)*50 + c)*256;
    __shared__ float red[256];
    red[t] = od[t];
    __syncthreads();
    for (int s = 128; s > 0; s >>= 1) {
        if (t < s) red[t] += red[t + s];
        __syncthreads();
    }
    float mean = red[0] * (1.f/256.f);
    g_a2c[(b*50 + c)*256 + t] = ev[t] + mean;
}

// ---------------------------------------------------------------------------
// K4: zero-upsample(2,4) + conv3 (50->50, 3x5 circular on 32x64) + relu.
// ---------------------------------------------------------------------------
__global__ void __launch_bounds__(128, 8)
k4(const float* __restrict__ w3, const float* __restrict__ b3) {
    __shared__ float sxd[50][2][16];
    const int b = blockIdx.y, bx = blockIdx.x;
    const int h = bx >> 1, cog = bx & 1;
    const int tid = threadIdx.x;
    const int hodd = h & 1;
    const int pA = hodd ? 1 : 0;
    const int rowA = ((h - pA) & 31) >> 1;
    const int rowB = ((h - 2) & 31) >> 1;
    for (int idx = tid; idx < 1600; idx += 128) {
        int cin = idx >> 5, slot = (idx >> 4) & 1, col = idx & 15;
        int row = slot ? rowB : rowA;
        sxd[cin][slot][col] = g_a2c[((b*50 + cin)*16 + row)*16 + col];
    }
    __syncthreads();

    if (tid < 100) {
        const int co = cog*25 + (tid >> 2), cls = tid & 3;
        float acc[16];
        #pragma unroll
        for (int j = 0; j < 16; j++) acc[j] = 0.f;

        #pragma unroll 2
        for (int cin = 0; cin < 50; cin++) {
            const float* wp = w3 + (co*50 + cin)*15;
            {
                float xr[16];
                #pragma unroll
                for (int jj = 0; jj < 4; jj++) {
                    float4 v = *(const float4*)&sxd[cin][0][jj*4];
                    xr[jj*4+0] = v.x; xr[jj*4+1] = v.y;
                    xr[jj*4+2] = v.z; xr[jj*4+3] = v.w;
                }
                float w0 = __ldg(&wp[pA*5 + cls]);
                #pragma unroll
                for (int j = 0; j < 16; j++) acc[j] += w0 * xr[j];
                if (cls == 0) {
                    float w1 = __ldg(&wp[pA*5 + 4]);
                    #pragma unroll
                    for (int j = 0; j < 16; j++)
                        acc[j] += w1 * xr[(j + 15) & 15];
                }
            }
            if (!hodd) {
                float xr[16];
                #pragma unroll
                for (int jj = 0; jj < 4; jj++) {
                    float4 v = *(const float4*)&sxd[cin][1][jj*4];
                    xr[jj*4+0] = v.x; xr[jj*4+1] = v.y;
                    xr[jj*4+2] = v.z; xr[jj*4+3] = v.w;
                }
                float w0 = __ldg(&wp[10 + cls]);
                #pragma unroll
                for (int j = 0; j < 16; j++) acc[j] += w0 * xr[j];
                if (cls == 0) {
                    float w1 = __ldg(&wp[10 + 4]);
                    #pragma unroll
                    for (int j = 0; j < 16; j++)
                        acc[j] += w1 * xr[(j + 15) & 15];
                }
            }
        }
        float bb = b3[co];
        #pragma unroll
        for (int j = 0; j < 16; j++)
            g_a3[((b*50 + co)*32 + h)*64 + cls + 4*j] =
                fmaxf(acc[j] + bb, 0.f);
    }
}

// ---------------------------------------------------------------------------
// K5: zero-upsample(2,4) + conv4 (50->50, 3x7 circular on 64x256) + relu.
// ---------------------------------------------------------------------------
__global__ void __launch_bounds__(224, 3)
k5(const float* __restrict__ w4, const float* __restrict__ b4) {
    __shared__ float2 sxd[50][2][18];
    const int bp = blockIdx.y, bx = blockIdx.x;
    const int h = bx >> 2, qt = bx & 3;
    const int b0 = 2*bp, b1i = 2*bp + 1;
    const int tid = threadIdx.x;
    const int hodd = h & 1;
    const int pA = hodd ? 1 : 0;
    const int rowA = ((h - pA) & 63) >> 1;
    const int rowB = ((h - 2) & 63) >> 1;
    const float* a3b0 = g_a3 + b0*50*2048;
    const float* a3b1 = g_a3 + b1i*50*2048;
    for (int idx = tid; idx < 50*2*17; idx += 224) {
        int cin = idx / 34, s2 = idx % 34;
        int slot = s2 / 17, k = s2 % 17;
        int m = (qt*16 - 1 + k) & 63;
        int row = slot ? rowB : rowA;
        int off = (cin*32 + row)*64 + m;
        sxd[cin][slot][k] = make_float2(a3b0[off], a3b1[off]);
    }
    __syncthreads();

    if (tid < 200) {
        const int co = tid >> 2, cls = tid & 3;
        u64 acc[16];
        #pragma unroll
        for (int j = 0; j < 16; j++) acc[j] = 0ULL;

        for (int cin = 0; cin < 50; cin++) {
            const float* wp = w4 + (co*50 + cin)*21;
            {
                u64 xr[17];
                #pragma unroll
                for (int jj = 0; jj < 8; jj++) {
                    ulonglong2 v = *(const ulonglong2*)&sxd[cin][0][jj*2];
                    xr[jj*2] = v.x; xr[jj*2+1] = v.y;
                }
                xr[16] = lds2(&sxd[cin][0][16]);
                float w0s = __ldg(&wp[pA*7 + cls]);
                u64 w0 = pk2(w0s, w0s);
                #pragma unroll
                for (int j = 0; j < 16; j++) fma2(acc[j], xr[j+1], w0);
                if (cls < 3) {
                    float w1s = __ldg(&wp[pA*7 + cls + 4]);
                    u64 w1 = pk2(w1s, w1s);
                    #pragma unroll
                    for (int j = 0; j < 16; j++) fma2(acc[j], xr[j], w1);
                }
            }
            if (!hodd) {
                u64 xr[17];
                #pragma unroll
                for (int jj = 0; jj < 8; jj++) {
                    ulonglong2 v = *(const ulonglong2*)&sxd[cin][1][jj*2];
                    xr[jj*2] = v.x; xr[jj*2+1] = v.y;
                }
                xr[16] = lds2(&sxd[cin][1][16]);
                float w0s = __ldg(&wp[14 + cls]);
                u64 w0 = pk2(w0s, w0s);
                #pragma unroll
                for (int j = 0; j < 16; j++) fma2(acc[j], xr[j+1], w0);
                if (cls < 3) {
                    float w1s = __ldg(&wp[14 + cls + 4]);
                    u64 w1 = pk2(w1s, w1s);
                    #pragma unroll
                    for (int j = 0; j < 16; j++) fma2(acc[j], xr[j], w1);
                }
            }
        }
        float bb = b4[co];
        #pragma unroll
        for (int j = 0; j < 16; j++) {
            float2 a = up2(acc[j]);
            int off = (co*64 + h)*256 + cls + 4*(qt*16 + j);
            g_a4[b0 *50*16384 + off] = fmaxf(a.x + bb, 0.f);
            g_a4[b1i*50*16384 + off] = fmaxf(a.y + bb, 0.f);
        }
    }
}

// ---------------------------------------------------------------------------
// K6: conv5 (50->1, 3x7 circular on 64x256) + sigmoid. Scalar.
// ---------------------------------------------------------------------------
__global__ void __launch_bounds__(128, 4)
k6(const float* __restrict__ w5, const float* __restrict__ b5,
   float* __restrict__ out) {
    __shared__ float sxc[5][4][320];
    __shared__ float sw[1050];
    const int b = blockIdx.y, hp = blockIdx.x;
    const int h0 = hp*2;
    const int tid = threadIdx.x;
    const int colg = tid & 63, i = tid >> 6;
    const float* a4b = g_a4 + b*50*16384;
    for (int idx = tid; idx < 1050; idx += 128) sw[idx] = w5[idx];

    float acc[4];
    #pragma unroll
    for (int c = 0; c < 4; c++) acc[c] = 0.f;

    #pragma unroll 1
    for (int cb = 0; cb < 50; cb += 5) {
        __syncthreads();
        for (int idx = tid; idx < 5*4*256; idx += 128) {
            int cl = idx >> 10, rr = (idx >> 8) & 3, m = idx & 255;
            int inrow = (h0 - 2 + rr) & 63;
            sxc[cl][rr][m + (m >> 2)] = a4b[((cb + cl)*64 + inrow)*256 + m];
        }
        __syncthreads();
        #pragma unroll 1
        for (int cl = 0; cl < 5; cl++) {
            float wv[21];
            #pragma unroll
            for (int t = 0; t < 21; t++) wv[t] = sw[(cb + cl)*21 + t];
            #pragma unroll
            for (int dp = 0; dp < 3; dp++) {
                int rr = i + dp;
                int p = 2 - dp;
                float xv[10];
                #pragma unroll
                for (int j = 0; j < 10; j++) {
                    int m = (colg*4 - 6 + j) & 255;
                    xv[j] = sxc[cl][rr][m + (m >> 2)];
                }
                #pragma unroll
                for (int q = 0; q < 7; q++) {
                    float w = wv[p*7 + q];
                    #pragma unroll
                    for (int c = 0; c < 4; c++)
                        acc[c] += w * xv[c + 6 - q];
                }
            }
        }
    }
    float bb = b5[0];
    #pragma unroll
    for (int c = 0; c < 4; c++) {
        float z = acc[c] + bb;
        out[(b*64 + h0 + i)*256 + colg*4 + c] = 1.f / (1.f + expf(-z));
    }
}

// ---------------------------------------------------------------------------
extern "C" void kernel_launch(void* const* d_in, const int* in_sizes, int n_in,
                              void* d_out, int out_size) {
    const float* x  = (const float*)d_in[0];
    const float* w1 = (const float*)d_in[1];
    const float* b1 = (const float*)d_in[2];
    const float* w2 = (const float*)d_in[3];
    const float* b2 = (const float*)d_in[4];
    const float* w3 = (const float*)d_in[5];
    const float* b3 = (const float*)d_in[6];
    const float* w4 = (const float*)d_in[7];
    const float* b4 = (const float*)d_in[8];
    const float* w5 = (const float*)d_in[9];
    const float* b5 = (const float*)d_in[10];
    float* out = (float*)d_out;

    static bool attr_set = false;
    if (!attr_set) {
        cudaFuncSetAttribute(k2m, cudaFuncAttributeMaxDynamicSharedMemorySize,
                             81920);
        attr_set = true;
    }

    k2w<<<21, 256>>>(w2);                       // idx 0
    k1<<<dim3(8, 32), 256>>>(x, w1, b1);        // idx 1
    knop<<<1, 32>>>();                          // idx 2
    k2m<<<dim3(16, 16), 256, 81920>>>(b2);      // idx 3 <- ncu capture
    k3<<<800, 256>>>();
    k4<<<dim3(64, 16), 128>>>(w3, b3);
    k5<<<dim3(256, 8), 224>>>(w4, b4);
    k6<<<dim3(32, 16), 128>>>(w5, b5, out);
}

// round 16
// speedup vs baseline: 1.2562x; 1.2562x over previous
#include <cuda_runtime.h>
#include <cuda_bf16.h>
#include <cstdint>
#include <math.h>

// ---- packed f32x2 helpers ------------------------------------------------
typedef unsigned long long u64;
__device__ __forceinline__ u64 pk2(float lo, float hi) {
    u64 r; asm("mov.b64 %0, {%1, %2};" : "=l"(r) : "f"(lo), "f"(hi)); return r;
}
__device__ __forceinline__ float2 up2(u64 v) {
    float2 r; asm("mov.b64 {%0, %1}, %2;" : "=f"(r.x), "=f"(r.y) : "l"(v)); return r;
}
__device__ __forceinline__ void fma2(u64& d, u64 a, u64 b) {
    asm("fma.rn.f32x2 %0, %1, %2, %0;" : "+l"(d) : "l"(a), "l"(b));
}
__device__ __forceinline__ u64 lds2(const float2* p) { return *(const u64*)p; }
__device__ __forceinline__ int swz(int m) { return m + (m >> 3); }

__device__ __forceinline__ uint32_t smem_u32(const void* p) {
    uint32_t a;
    asm("{ .reg .u64 t; cvta.to.shared.u64 t, %1; cvt.u32.u64 %0, t; }"
        : "=r"(a) : "l"(p));
    return a;
}
#define SMEM_SWZ128(o) ((o) ^ (((o) >> 3) & 0x70))

// ---- warp-level mma.sync helpers -----------------------------------------
__device__ __forceinline__ void ldmx4(uint32_t& a0, uint32_t& a1,
                                      uint32_t& a2, uint32_t& a3, uint32_t addr) {
    asm volatile("ldmatrix.sync.aligned.m8n8.x4.shared.b16 {%0,%1,%2,%3}, [%4];"
                 : "=r"(a0), "=r"(a1), "=r"(a2), "=r"(a3) : "r"(addr));
}
__device__ __forceinline__ void ldmx2(uint32_t& b0, uint32_t& b1, uint32_t addr) {
    asm volatile("ldmatrix.sync.aligned.m8n8.x2.shared.b16 {%0,%1}, [%2];"
                 : "=r"(b0), "=r"(b1) : "r"(addr));
}
__device__ __forceinline__ void mma16816(float* c, uint32_t a0, uint32_t a1,
                                         uint32_t a2, uint32_t a3,
                                         uint32_t b0, uint32_t b1) {
    asm volatile(
        "mma.sync.aligned.m16n8k16.row.col.f32.bf16.bf16.f32 "
        "{%0,%1,%2,%3}, {%4,%5,%6,%7}, {%8,%9}, {%0,%1,%2,%3};"
        : "+f"(c[0]), "+f"(c[1]), "+f"(c[2]), "+f"(c[3])
        : "r"(a0), "r"(a1), "r"(a2), "r"(a3), "r"(b0), "r"(b1));
}

// Intermediate activations (static device globals).
__device__ float g_a1[32*50*32*64];
__device__ float g_a2[32*50*16*16];
__device__ float g_a2c[16*50*16*16];
__device__ float g_a3[16*50*32*64];
__device__ float g_a4[16*50*64*256];
// bf16 hi/lo transposed+halo activations for MMA k2: [h32][w'70][b32][cin64]
__device__ __nv_bfloat16 g_a1t_hi[32*70*32*64];
__device__ __nv_bfloat16 g_a1t_lo[32*70*32*64];
// prepped weights: [tap21][hi/lo 2][co64][cin64]
__device__ __nv_bfloat16 g_w2t[21*2*64*64];

// ---------------------------------------------------------------------------
// K2W: weight prep: w2[50,50,3,7] fp32 -> g_w2t bf16 hi/lo, zero-padded.
// ---------------------------------------------------------------------------
__global__ void k2w(const float* __restrict__ w2) {
    const int tap = blockIdx.x;          // 0..20
    const int p = tap / 7, q = tap % 7;
    for (int idx = threadIdx.x; idx < 4096; idx += 256) {
        int co = idx >> 6, cin = idx & 63;
        float v = 0.f;
        if (co < 50 && cin < 50)
            v = w2[((co*50 + cin)*3 + p)*7 + q];
        __nv_bfloat16 hi = __float2bfloat16(v);
        __nv_bfloat16 lo = __float2bfloat16(v - __bfloat162float(hi));
        g_w2t[(tap*2 + 0)*4096 + idx] = hi;
        g_w2t[(tap*2 + 1)*4096 + idx] = lo;
    }
}

// ---------------------------------------------------------------------------
// K1: circular conv1 (1->50, 3x7 on 64x256) + maxpool(2,4) + relu.
// (Proven R5/R10 version — coalesced fp32 output.)
// ---------------------------------------------------------------------------
__global__ void k1(const float* __restrict__ x, const float* __restrict__ w1,
                   const float* __restrict__ b1) {
    __shared__ float sx[10][256];
    __shared__ float sw[50*21];
    const int b = blockIdx.y, strip = blockIdx.x;
    const int tid = threadIdx.x;
    const float* xb = x + b*64*256;
    for (int idx = tid; idx < 10*256; idx += 256) {
        int l = idx >> 8, col = idx & 255;
        int row = (strip*8 - 2 + l) & 63;
        sx[l][col] = xb[row*256 + col];
    }
    for (int idx = tid; idx < 1050; idx += 256) sw[idx] = w1[idx];
    __syncthreads();

    const int prl = tid >> 6;
    const int pw  = tid & 63;
    float xv[4][10];
    #pragma unroll
    for (int rl = 0; rl < 4; rl++)
        #pragma unroll
        for (int j = 0; j < 10; j++)
            xv[rl][j] = sx[prl*2 + rl][(pw*4 - 6 + j) & 255];

    const int pr = strip*4 + prl;
    for (int co = 0; co < 50; co++) {
        float acc[8];
        #pragma unroll
        for (int i = 0; i < 8; i++) acc[i] = 0.f;
        #pragma unroll
        for (int p = 0; p < 3; p++)
            #pragma unroll
            for (int q = 0; q < 7; q++) {
                float wv = sw[co*21 + p*7 + q];
                #pragma unroll
                for (int dr = 0; dr < 2; dr++)
                    #pragma unroll
                    for (int dc = 0; dc < 4; dc++)
                        acc[dr*4+dc] += wv * xv[dr + 2 - p][dc + 6 - q];
            }
        float m = acc[0];
        #pragma unroll
        for (int i = 1; i < 8; i++) m = fmaxf(m, acc[i]);
        g_a1[((b*50 + co)*32 + pr)*64 + pw] = fmaxf(m + b1[co], 0.f);
    }
}

// ---------------------------------------------------------------------------
// K1T: transpose g_a1 [b,co,h,w] -> g_a1t_{hi,lo} [h][w'70][b][cin64] bf16.
// grid (32 h, 32 b), 256 threads; coalesced reads + 16B-chunk writes.
// ---------------------------------------------------------------------------
__global__ void k1t() {
    __shared__ float tile[50][65];
    const int h = blockIdx.x, b = blockIdx.y;
    const int tid = threadIdx.x;
    for (int idx = tid; idx < 3200; idx += 256) {
        int co = idx >> 6, w = idx & 63;
        tile[co][w] = g_a1[((b*50 + co)*32 + h)*64 + w];
    }
    __syncthreads();
    // 70 w' rows x 8 chunks x 2 (hi/lo) = 1120 uint4 writes
    for (int idx = tid; idx < 1120; idx += 256) {
        int hl = idx / 560;
        int rest = idx - hl*560;
        int wp = rest >> 3, ch = rest & 7;
        int w = (wp + 58) & 63;      // (wp - 6) mod 64
        __nv_bfloat16 v[8];
        #pragma unroll
        for (int i = 0; i < 8; i++) {
            int c = ch*8 + i;
            float val = (c < 50) ? tile[c][w] : 0.f;
            __nv_bfloat16 hi = __float2bfloat16(val);
            if (hl == 0) v[i] = hi;
            else         v[i] = __float2bfloat16(val - __bfloat162float(hi));
        }
        __nv_bfloat16* dst = (hl ? g_a1t_lo : g_a1t_hi)
            + (((h*70 + wp)*32 + b) << 6) + (ch << 3);
        *(uint4*)dst = *(const uint4*)v;
    }
}

// ---------------------------------------------------------------------------
// K2M: conv2 + maxpool + relu via mma.sync bf16 shift-GEMM (hi/lo 3-pass).
// Block = (pooled row r, batch b), 256 threads (8 warps = dh2 x strip4).
// A halo staged ONCE: 8 tiles (4 h-rows x hi/lo), 70 rows x 128B each.
// Tap shift = +(6-q) row offset into halo tile; h-row choice = tile index.
// Per tap only the 16KB weight pair is staged. N=64 co, K=64 cin.
// smem: A halo 8x9216 @0 (73728), W 2x8192 @73728; total 90112.
// Epilogue: D[2][64][65] f32 (33.3KB) reuses arena; pool 2x4+bias+relu.
// ---------------------------------------------------------------------------
extern __shared__ __align__(1024) char k2m_arena[];
__global__ void __launch_bounds__(256, 2)
k2m(const float* __restrict__ b2) {
    const int r = blockIdx.x, b = blockIdx.y;
    const int tid = threadIdx.x;
    const int wid = tid >> 5, lid = tid & 31;
    char* arena = k2m_arena;
    const uint32_t abase0 = smem_u32(arena);
    const uint32_t wbase0 = smem_u32(arena + 73728);
    const int dh = wid >> 2, strip = wid & 3;

    // stage A halo once: tile t = j*2+hl, j -> hin = (2r-2+j)&31
    for (int it = tid; it < 4480; it += 256) {
        int t = it / 560;
        int rc = it - t*560;
        int row = rc >> 3, ch = rc & 7;
        int j = t >> 1, hl = t & 1;
        int hin = (2*r - 2 + j) & 31;
        const __nv_bfloat16* src = (hl ? g_a1t_lo : g_a1t_hi)
            + (((hin*70 + row)*32 + b) << 6) + (ch << 3);
        uint4 v = *(const uint4*)src;
        *(uint4*)(arena + t*9216 + SMEM_SWZ128((row << 7) + (ch << 4))) = v;
    }

    float acc[8][4];
    #pragma unroll
    for (int nt = 0; nt < 8; nt++)
        #pragma unroll
        for (int i = 0; i < 4; i++) acc[nt][i] = 0.f;

    for (int tap = 0; tap < 21; tap++) {
        const int p = tap / 7, q = tap % 7;
        __syncthreads();          // protect W buffer (and first-iter A halo)
        for (int it = tid; it < 1024; it += 256) {
            int hl = it >> 9;
            int rc = it & 511;
            int row = rc >> 3, ch = rc & 7;
            const __nv_bfloat16* src = g_w2t + (tap*2 + hl)*4096 + (row << 6) + (ch << 3);
            uint4 v = *(const uint4*)src;
            *(uint4*)(arena + 73728 + hl*8192 + SMEM_SWZ128((row << 7) + (ch << 4))) = v;
        }
        __syncthreads();

        const int j = dh - p + 2;                 // halo tile row-group
        const uint32_t at_hi = abase0 + (j*2 + 0)*9216;
        const uint32_t at_lo = abase0 + (j*2 + 1)*9216;
        const int rsh = 6 - q;                    // column shift as row offset

        #pragma unroll
        for (int pass = 0; pass < 3; pass++) {
            const uint32_t ab = (pass == 2) ? at_lo : at_hi;
            const uint32_t wb = wbase0 + ((pass == 1) ? 8192 : 0);
            #pragma unroll
            for (int kk = 0; kk < 4; kk++) {
                uint32_t bf[8][2];
                {
                    int rowb = (lid & 7);
                    int kc = kk*16 + ((lid & 8) ? 8 : 0);
                    #pragma unroll
                    for (int nt = 0; nt < 8; nt++) {
                        uint32_t addr = wb +
                            SMEM_SWZ128((((nt << 3) + rowb) << 7) + (kc << 1));
                        ldmx2(bf[nt][0], bf[nt][1], addr);
                    }
                }
                uint32_t a0, a1, a2, a3;
                int rowa = strip*16 + (lid & 15) + rsh;
                int kca = kk*16 + ((lid >> 4) << 3);
                uint32_t addr = ab + SMEM_SWZ128((rowa << 7) + (kca << 1));
                ldmx4(a0, a1, a2, a3, addr);
                #pragma unroll
                for (int nt = 0; nt < 8; nt++)
                    mma16816(acc[nt], a0, a1, a2, a3, bf[nt][0], bf[nt][1]);
            }
        }
    }
    __syncthreads();   // tiles dead; arena reused for D staging

    float* Dsm = (float*)arena;          // [2][64][65]
    {
        int r0 = strip*16 + (lid >> 2);
        int c0 = (lid & 3)*2;
        #pragma unroll
        for (int nt = 0; nt < 8; nt++) {
            int c = nt*8 + c0;
            Dsm[(dh*64 + r0)*65 + c]       = acc[nt][0];
            Dsm[(dh*64 + r0)*65 + c + 1]   = acc[nt][1];
            Dsm[(dh*64 + r0 + 8)*65 + c]     = acc[nt][2];
            Dsm[(dh*64 + r0 + 8)*65 + c + 1] = acc[nt][3];
        }
    }
    __syncthreads();

    // maxpool(2h x 4w) + bias + relu -> g_a2[b, co, r, pw]
    for (int idx = tid; idx < 800; idx += 256) {
        int co = idx >> 4, pw = idx & 15;
        float mx = -1e30f;
        #pragma unroll
        for (int dhh = 0; dhh < 2; dhh++)
            #pragma unroll
            for (int dw = 0; dw < 4; dw++)
                mx = fmaxf(mx, Dsm[(dhh*64 + pw*4 + dw)*65 + co]);
        g_a2[((b*50 + co)*16 + r)*16 + pw] = fmaxf(mx + b2[co], 0.f);
    }
}

// ---------------------------------------------------------------------------
// K3: combine: out[b] = a2[2b] + mean_{hw}(a2[2b+1]).  grid 800 = 16*50.
// ---------------------------------------------------------------------------
__global__ void k3() {
    const int bc = blockIdx.x;
    const int b = bc / 50, c = bc % 50;
    const int t = threadIdx.x;
    const float* ev = g_a2 + ((2*b)*50 + c)*256;
    const float* od = g_a2 + ((2*b + 1)*50 + c)*256;
    __shared__ float red[256];
    red[t] = od[t];
    __syncthreads();
    for (int s = 128; s > 0; s >>= 1) {
        if (t < s) red[t] += red[t + s];
        __syncthreads();
    }
    float mean = red[0] * (1.f/256.f);
    g_a2c[(b*50 + c)*256 + t] = ev[t] + mean;
}

// ---------------------------------------------------------------------------
// K4: zero-upsample(2,4) + conv3 (50->50, 3x5 circular on 32x64) + relu.
// ---------------------------------------------------------------------------
__global__ void __launch_bounds__(128, 8)
k4(const float* __restrict__ w3, const float* __restrict__ b3) {
    __shared__ float sxd[50][2][16];
    const int b = blockIdx.y, bx = blockIdx.x;
    const int h = bx >> 1, cog = bx & 1;
    const int tid = threadIdx.x;
    const int hodd = h & 1;
    const int pA = hodd ? 1 : 0;
    const int rowA = ((h - pA) & 31) >> 1;
    const int rowB = ((h - 2) & 31) >> 1;
    for (int idx = tid; idx < 1600; idx += 128) {
        int cin = idx >> 5, slot = (idx >> 4) & 1, col = idx & 15;
        int row = slot ? rowB : rowA;
        sxd[cin][slot][col] = g_a2c[((b*50 + cin)*16 + row)*16 + col];
    }
    __syncthreads();

    if (tid < 100) {
        const int co = cog*25 + (tid >> 2), cls = tid & 3;
        float acc[16];
        #pragma unroll
        for (int j = 0; j < 16; j++) acc[j] = 0.f;

        #pragma unroll 2
        for (int cin = 0; cin < 50; cin++) {
            const float* wp = w3 + (co*50 + cin)*15;
            {
                float xr[16];
                #pragma unroll
                for (int jj = 0; jj < 4; jj++) {
                    float4 v = *(const float4*)&sxd[cin][0][jj*4];
                    xr[jj*4+0] = v.x; xr[jj*4+1] = v.y;
                    xr[jj*4+2] = v.z; xr[jj*4+3] = v.w;
                }
                float w0 = __ldg(&wp[pA*5 + cls]);
                #pragma unroll
                for (int j = 0; j < 16; j++) acc[j] += w0 * xr[j];
                if (cls == 0) {
                    float w1 = __ldg(&wp[pA*5 + 4]);
                    #pragma unroll
                    for (int j = 0; j < 16; j++)
                        acc[j] += w1 * xr[(j + 15) & 15];
                }
            }
            if (!hodd) {
                float xr[16];
                #pragma unroll
                for (int jj = 0; jj < 4; jj++) {
                    float4 v = *(const float4*)&sxd[cin][1][jj*4];
                    xr[jj*4+0] = v.x; xr[jj*4+1] = v.y;
                    xr[jj*4+2] = v.z; xr[jj*4+3] = v.w;
                }
                float w0 = __ldg(&wp[10 + cls]);
                #pragma unroll
                for (int j = 0; j < 16; j++) acc[j] += w0 * xr[j];
                if (cls == 0) {
                    float w1 = __ldg(&wp[10 + 4]);
                    #pragma unroll
                    for (int j = 0; j < 16; j++)
                        acc[j] += w1 * xr[(j + 15) & 15];
                }
            }
        }
        float bb = b3[co];
        #pragma unroll
        for (int j = 0; j < 16; j++)
            g_a3[((b*50 + co)*32 + h)*64 + cls + 4*j] =
                fmaxf(acc[j] + bb, 0.f);
    }
}

// ---------------------------------------------------------------------------
// K5: zero-upsample(2,4) + conv4 (50->50, 3x7 circular on 64x256) + relu.
// ---------------------------------------------------------------------------
__global__ void __launch_bounds__(224, 3)
k5(const float* __restrict__ w4, const float* __restrict__ b4) {
    __shared__ float2 sxd[50][2][18];
    const int bp = blockIdx.y, bx = blockIdx.x;
    const int h = bx >> 2, qt = bx & 3;
    const int b0 = 2*bp, b1i = 2*bp + 1;
    const int tid = threadIdx.x;
    const int hodd = h & 1;
    const int pA = hodd ? 1 : 0;
    const int rowA = ((h - pA) & 63) >> 1;
    const int rowB = ((h - 2) & 63) >> 1;
    const float* a3b0 = g_a3 + b0*50*2048;
    const float* a3b1 = g_a3 + b1i*50*2048;
    for (int idx = tid; idx < 50*2*17; idx += 224) {
        int cin = idx / 34, s2 = idx % 34;
        int slot = s2 / 17, k = s2 % 17;
        int m = (qt*16 - 1 + k) & 63;
        int row = slot ? rowB : rowA;
        int off = (cin*32 + row)*64 + m;
        sxd[cin][slot][k] = make_float2(a3b0[off], a3b1[off]);
    }
    __syncthreads();

    if (tid < 200) {
        const int co = tid >> 2, cls = tid & 3;
        u64 acc[16];
        #pragma unroll
        for (int j = 0; j < 16; j++) acc[j] = 0ULL;

        for (int cin = 0; cin < 50; cin++) {
            const float* wp = w4 + (co*50 + cin)*21;
            {
                u64 xr[17];
                #pragma unroll
                for (int jj = 0; jj < 8; jj++) {
                    ulonglong2 v = *(const ulonglong2*)&sxd[cin][0][jj*2];
                    xr[jj*2] = v.x; xr[jj*2+1] = v.y;
                }
                xr[16] = lds2(&sxd[cin][0][16]);
                float w0s = __ldg(&wp[pA*7 + cls]);
                u64 w0 = pk2(w0s, w0s);
                #pragma unroll
                for (int j = 0; j < 16; j++) fma2(acc[j], xr[j+1], w0);
                if (cls < 3) {
                    float w1s = __ldg(&wp[pA*7 + cls + 4]);
                    u64 w1 = pk2(w1s, w1s);
                    #pragma unroll
                    for (int j = 0; j < 16; j++) fma2(acc[j], xr[j], w1);
                }
            }
            if (!hodd) {
                u64 xr[17];
                #pragma unroll
                for (int jj = 0; jj < 8; jj++) {
                    ulonglong2 v = *(const ulonglong2*)&sxd[cin][1][jj*2];
                    xr[jj*2] = v.x; xr[jj*2+1] = v.y;
                }
                xr[16] = lds2(&sxd[cin][1][16]);
                float w0s = __ldg(&wp[14 + cls]);
                u64 w0 = pk2(w0s, w0s);
                #pragma unroll
                for (int j = 0; j < 16; j++) fma2(acc[j], xr[j+1], w0);
                if (cls < 3) {
                    float w1s = __ldg(&wp[14 + cls + 4]);
                    u64 w1 = pk2(w1s, w1s);
                    #pragma unroll
                    for (int j = 0; j < 16; j++) fma2(acc[j], xr[j], w1);
                }
            }
        }
        float bb = b4[co];
        #pragma unroll
        for (int j = 0; j < 16; j++) {
            float2 a = up2(acc[j]);
            int off = (co*64 + h)*256 + cls + 4*(qt*16 + j);
            g_a4[b0 *50*16384 + off] = fmaxf(a.x + bb, 0.f);
            g_a4[b1i*50*16384 + off] = fmaxf(a.y + bb, 0.f);
        }
    }
}

// ---------------------------------------------------------------------------
// K6: conv5 (50->1, 3x7 circular on 64x256) + sigmoid. Scalar.
// ---------------------------------------------------------------------------
__global__ void __launch_bounds__(128, 4)
k6(const float* __restrict__ w5, const float* __restrict__ b5,
   float* __restrict__ out) {
    __shared__ float sxc[5][4][320];
    __shared__ float sw[1050];
    const int b = blockIdx.y, hp = blockIdx.x;
    const int h0 = hp*2;
    const int tid = threadIdx.x;
    const int colg = tid & 63, i = tid >> 6;
    const float* a4b = g_a4 + b*50*16384;
    for (int idx = tid; idx < 1050; idx += 128) sw[idx] = w5[idx];

    float acc[4];
    #pragma unroll
    for (int c = 0; c < 4; c++) acc[c] = 0.f;

    #pragma unroll 1
    for (int cb = 0; cb < 50; cb += 5) {
        __syncthreads();
        for (int idx = tid; idx < 5*4*256; idx += 128) {
            int cl = idx >> 10, rr = (idx >> 8) & 3, m = idx & 255;
            int inrow = (h0 - 2 + rr) & 63;
            sxc[cl][rr][m + (m >> 2)] = a4b[((cb + cl)*64 + inrow)*256 + m];
        }
        __syncthreads();
        #pragma unroll 1
        for (int cl = 0; cl < 5; cl++) {
            float wv[21];
            #pragma unroll
            for (int t = 0; t < 21; t++) wv[t] = sw[(cb + cl)*21 + t];
            #pragma unroll
            for (int dp = 0; dp < 3; dp++) {
                int rr = i + dp;
                int p = 2 - dp;
                float xv[10];
                #pragma unroll
                for (int j = 0; j < 10; j++) {
                    int m = (colg*4 - 6 + j) & 255;
                    xv[j] = sxc[cl][rr][m + (m >> 2)];
                }
                #pragma unroll
                for (int q = 0; q < 7; q++) {
                    float w = wv[p*7 + q];
                    #pragma unroll
                    for (int c = 0; c < 4; c++)
                        acc[c] += w * xv[c + 6 - q];
                }
            }
        }
    }
    float bb = b5[0];
    #pragma unroll
    for (int c = 0; c < 4; c++) {
        float z = acc[c] + bb;
        out[(b*64 + h0 + i)*256 + colg*4 + c] = 1.f / (1.f + expf(-z));
    }
}

// ---------------------------------------------------------------------------
extern "C" void kernel_launch(void* const* d_in, const int* in_sizes, int n_in,
                              void* d_out, int out_size) {
    const float* x  = (const float*)d_in[0];
    const float* w1 = (const float*)d_in[1];
    const float* b1 = (const float*)d_in[2];
    const float* w2 = (const float*)d_in[3];
    const float* b2 = (const float*)d_in[4];
    const float* w3 = (const float*)d_in[5];
    const float* b3 = (const float*)d_in[6];
    const float* w4 = (const float*)d_in[7];
    const float* b4 = (const float*)d_in[8];
    const float* w5 = (const float*)d_in[9];
    const float* b5 = (const float*)d_in[10];
    float* out = (float*)d_out;

    static bool attr_set = false;
    if (!attr_set) {
        cudaFuncSetAttribute(k2m, cudaFuncAttributeMaxDynamicSharedMemorySize,
                             90112);
        attr_set = true;
    }

    k2w<<<21, 256>>>(w2);                       // idx 0
    k1<<<dim3(8, 32), 256>>>(x, w1, b1);        // idx 1
    k1t<<<dim3(32, 32), 256>>>();               // idx 2
    k2m<<<dim3(16, 32), 256, 90112>>>(b2);      // idx 3 <- ncu capture
    k3<<<800, 256>>>();
    k4<<<dim3(64, 16), 128>>>(w3, b3);
    k5<<<dim3(256, 8), 224>>>(w4, b4);
    k6<<<dim3(32, 16), 128>>>(w5, b5, out);
}

// round 17
// speedup vs baseline: 1.3270x; 1.0564x over previous
#include <cuda_runtime.h>
#include <cuda_bf16.h>
#include <cstdint>
#include <math.h>

// ---- packed f32x2 helpers ------------------------------------------------
typedef unsigned long long u64;
__device__ __forceinline__ u64 pk2(float lo, float hi) {
    u64 r; asm("mov.b64 %0, {%1, %2};" : "=l"(r) : "f"(lo), "f"(hi)); return r;
}
__device__ __forceinline__ float2 up2(u64 v) {
    float2 r; asm("mov.b64 {%0, %1}, %2;" : "=f"(r.x), "=f"(r.y) : "l"(v)); return r;
}
__device__ __forceinline__ void fma2(u64& d, u64 a, u64 b) {
    asm("fma.rn.f32x2 %0, %1, %2, %0;" : "+l"(d) : "l"(a), "l"(b));
}
__device__ __forceinline__ u64 lds2(const float2* p) { return *(const u64*)p; }
__device__ __forceinline__ int swz(int m) { return m + (m >> 3); }

__device__ __forceinline__ uint32_t smem_u32(const void* p) {
    uint32_t a;
    asm("{ .reg .u64 t; cvta.to.shared.u64 t, %1; cvt.u32.u64 %0, t; }"
        : "=r"(a) : "l"(p));
    return a;
}
#define SMEM_SWZ128(o) ((o) ^ (((o) >> 3) & 0x70))

// ---- warp-level mma.sync helpers -----------------------------------------
__device__ __forceinline__ void ldmx4(uint32_t& a0, uint32_t& a1,
                                      uint32_t& a2, uint32_t& a3, uint32_t addr) {
    asm volatile("ldmatrix.sync.aligned.m8n8.x4.shared.b16 {%0,%1,%2,%3}, [%4];"
                 : "=r"(a0), "=r"(a1), "=r"(a2), "=r"(a3) : "r"(addr));
}
__device__ __forceinline__ void mma16816(float* c, uint32_t a0, uint32_t a1,
                                         uint32_t a2, uint32_t a3,
                                         uint32_t b0, uint32_t b1) {
    asm volatile(
        "mma.sync.aligned.m16n8k16.row.col.f32.bf16.bf16.f32 "
        "{%0,%1,%2,%3}, {%4,%5,%6,%7}, {%8,%9}, {%0,%1,%2,%3};"
        : "+f"(c[0]), "+f"(c[1]), "+f"(c[2]), "+f"(c[3])
        : "r"(a0), "r"(a1), "r"(a2), "r"(a3), "r"(b0), "r"(b1));
}

// Intermediate activations (static device globals).
__device__ float g_a1[32*50*32*64];
__device__ float g_a2[32*50*16*16];
__device__ float g_a2c[16*50*16*16];
__device__ float g_a3[16*50*32*64];
__device__ float g_a4[16*50*64*256];
// bf16 hi/lo transposed+halo activations for MMA k2: [h32][w'70][b32][cin64]
__device__ __nv_bfloat16 g_a1t_hi[32*70*32*64];
__device__ __nv_bfloat16 g_a1t_lo[32*70*32*64];
// prepped weights: [tap21][hi/lo 2][co64][cin64]
__device__ __nv_bfloat16 g_w2t[21*2*64*64];

// ---------------------------------------------------------------------------
// K2W: weight prep: w2[50,50,3,7] fp32 -> g_w2t bf16 hi/lo, zero-padded.
// ---------------------------------------------------------------------------
__global__ void k2w(const float* __restrict__ w2) {
    const int tap = blockIdx.x;          // 0..20
    const int p = tap / 7, q = tap % 7;
    for (int idx = threadIdx.x; idx < 4096; idx += 256) {
        int co = idx >> 6, cin = idx & 63;
        float v = 0.f;
        if (co < 50 && cin < 50)
            v = w2[((co*50 + cin)*3 + p)*7 + q];
        __nv_bfloat16 hi = __float2bfloat16(v);
        __nv_bfloat16 lo = __float2bfloat16(v - __bfloat162float(hi));
        g_w2t[(tap*2 + 0)*4096 + idx] = hi;
        g_w2t[(tap*2 + 1)*4096 + idx] = lo;
    }
}

// ---------------------------------------------------------------------------
// K1: circular conv1 (1->50, 3x7 on 64x256) + maxpool(2,4) + relu.
// ---------------------------------------------------------------------------
__global__ void k1(const float* __restrict__ x, const float* __restrict__ w1,
                   const float* __restrict__ b1) {
    __shared__ float sx[10][256];
    __shared__ float sw[50*21];
    const int b = blockIdx.y, strip = blockIdx.x;
    const int tid = threadIdx.x;
    const float* xb = x + b*64*256;
    for (int idx = tid; idx < 10*256; idx += 256) {
        int l = idx >> 8, col = idx & 255;
        int row = (strip*8 - 2 + l) & 63;
        sx[l][col] = xb[row*256 + col];
    }
    for (int idx = tid; idx < 1050; idx += 256) sw[idx] = w1[idx];
    __syncthreads();

    const int prl = tid >> 6;
    const int pw  = tid & 63;
    float xv[4][10];
    #pragma unroll
    for (int rl = 0; rl < 4; rl++)
        #pragma unroll
        for (int j = 0; j < 10; j++)
            xv[rl][j] = sx[prl*2 + rl][(pw*4 - 6 + j) & 255];

    const int pr = strip*4 + prl;
    for (int co = 0; co < 50; co++) {
        float acc[8];
        #pragma unroll
        for (int i = 0; i < 8; i++) acc[i] = 0.f;
        #pragma unroll
        for (int p = 0; p < 3; p++)
            #pragma unroll
            for (int q = 0; q < 7; q++) {
                float wv = sw[co*21 + p*7 + q];
                #pragma unroll
                for (int dr = 0; dr < 2; dr++)
                    #pragma unroll
                    for (int dc = 0; dc < 4; dc++)
                        acc[dr*4+dc] += wv * xv[dr + 2 - p][dc + 6 - q];
            }
        float m = acc[0];
        #pragma unroll
        for (int i = 1; i < 8; i++) m = fmaxf(m, acc[i]);
        g_a1[((b*50 + co)*32 + pr)*64 + pw] = fmaxf(m + b1[co], 0.f);
    }
}

// ---------------------------------------------------------------------------
// K1T: transpose g_a1 [b,co,h,w] -> g_a1t_{hi,lo} [h][w'70][b][cin64] bf16.
// ---------------------------------------------------------------------------
__global__ void k1t() {
    __shared__ float tile[50][65];
    const int h = blockIdx.x, b = blockIdx.y;
    const int tid = threadIdx.x;
    for (int idx = tid; idx < 3200; idx += 256) {
        int co = idx >> 6, w = idx & 63;
        tile[co][w] = g_a1[((b*50 + co)*32 + h)*64 + w];
    }
    __syncthreads();
    for (int idx = tid; idx < 1120; idx += 256) {
        int hl = idx / 560;
        int rest = idx - hl*560;
        int wp = rest >> 3, ch = rest & 7;
        int w = (wp + 58) & 63;      // (wp - 6) mod 64
        __nv_bfloat16 v[8];
        #pragma unroll
        for (int i = 0; i < 8; i++) {
            int c = ch*8 + i;
            float val = (c < 50) ? tile[c][w] : 0.f;
            __nv_bfloat16 hi = __float2bfloat16(val);
            if (hl == 0) v[i] = hi;
            else         v[i] = __float2bfloat16(val - __bfloat162float(hi));
        }
        __nv_bfloat16* dst = (hl ? g_a1t_lo : g_a1t_hi)
            + (((h*70 + wp)*32 + b) << 6) + (ch << 3);
        *(uint4*)dst = *(const uint4*)v;
    }
}

// ---------------------------------------------------------------------------
// K2M: conv2 + maxpool + relu via mma.sync bf16 shift-GEMM (hi/lo 3-pass).
// Block = (pooled row r, batch b), 256 threads (8 warps = dh2 x strip4).
// A halo staged ONCE (8 tiles, 70 rows x 128B). Weights staged 2 taps per
// sync window (32KB buffer, 22 syncs instead of 42). B frags via ldmx4
// (2 n-tiles per load). smem: A 73728 + W 32768 = 106496.
// ---------------------------------------------------------------------------
extern __shared__ __align__(1024) char k2m_arena[];
__global__ void __launch_bounds__(256, 2)
k2m(const float* __restrict__ b2) {
    const int r = blockIdx.x, b = blockIdx.y;
    const int tid = threadIdx.x;
    const int wid = tid >> 5, lid = tid & 31;
    char* arena = k2m_arena;
    const uint32_t abase0 = smem_u32(arena);
    const uint32_t wbase0 = smem_u32(arena + 73728);
    const int dh = wid >> 2, strip = wid & 3;

    // stage A halo once: tile t = j*2+hl, j -> hin = (2r-2+j)&31
    for (int it = tid; it < 4480; it += 256) {
        int t = it / 560;
        int rc = it - t*560;
        int row = rc >> 3, ch = rc & 7;
        int j = t >> 1, hl = t & 1;
        int hin = (2*r - 2 + j) & 31;
        const __nv_bfloat16* src = (hl ? g_a1t_lo : g_a1t_hi)
            + (((hin*70 + row)*32 + b) << 6) + (ch << 3);
        uint4 v = *(const uint4*)src;
        *(uint4*)(arena + t*9216 + SMEM_SWZ128((row << 7) + (ch << 4))) = v;
    }

    float acc[8][4];
    #pragma unroll
    for (int nt = 0; nt < 8; nt++)
        #pragma unroll
        for (int i = 0; i < 4; i++) acc[nt][i] = 0.f;

    for (int tt = 0; tt < 11; tt++) {
        const int tap0 = tt*2;
        const int ntaps = (tt < 10) ? 2 : 1;
        __syncthreads();          // protect W buffer (and first-iter A halo)
        for (int it = tid; it < ntaps*1024; it += 256) {
            int tl = it >> 10;             // tap within pair
            int rc = it & 1023;
            int hl = rc >> 9;
            int rc2 = rc & 511;
            int row = rc2 >> 3, ch = rc2 & 7;
            const __nv_bfloat16* src =
                g_w2t + ((tap0 + tl)*2 + hl)*4096 + (row << 6) + (ch << 3);
            uint4 v = *(const uint4*)src;
            *(uint4*)(arena + 73728 + (tl*2 + hl)*8192 +
                      SMEM_SWZ128((row << 7) + (ch << 4))) = v;
        }
        __syncthreads();

        for (int tl = 0; tl < ntaps; tl++) {
            const int tap = tap0 + tl;
            const int p = tap / 7, q = tap % 7;
            const int j = dh - p + 2;                 // halo tile row-group
            const uint32_t at_hi = abase0 + (j*2 + 0)*9216;
            const uint32_t at_lo = abase0 + (j*2 + 1)*9216;
            const int rsh = 6 - q;                    // column shift (rows)

            #pragma unroll
            for (int pass = 0; pass < 3; pass++) {
                const uint32_t ab = (pass == 2) ? at_lo : at_hi;
                const uint32_t wb = wbase0 + tl*16384 +
                                    ((pass == 1) ? 8192 : 0);
                #pragma unroll
                for (int kk = 0; kk < 4; kk++) {
                    // B frags: 4 x ldmx4, each covers 2 n-tiles x 2 k-halves
                    uint32_t bf[8][2];
                    {
                        int ntl = (lid >> 4) & 1;         // n-tile within pair
                        int kc = kk*16 + ((lid & 8) ? 8 : 0);
                        int rowb = lid & 7;
                        #pragma unroll
                        for (int np = 0; np < 4; np++) {
                            int nrow = (np*2 + ntl)*8 + rowb;
                            uint32_t addr = wb +
                                SMEM_SWZ128((nrow << 7) + (kc << 1));
                            ldmx4(bf[np*2][0], bf[np*2][1],
                                  bf[np*2+1][0], bf[np*2+1][1], addr);
                        }
                    }
                    uint32_t a0, a1, a2, a3;
                    int rowa = strip*16 + (lid & 15) + rsh;
                    int kca = kk*16 + ((lid >> 4) << 3);
                    uint32_t addr = ab + SMEM_SWZ128((rowa << 7) + (kca << 1));
                    ldmx4(a0, a1, a2, a3, addr);
                    #pragma unroll
                    for (int nt = 0; nt < 8; nt++)
                        mma16816(acc[nt], a0, a1, a2, a3,
                                 bf[nt][0], bf[nt][1]);
                }
            }
        }
    }
    __syncthreads();   // tiles dead; arena reused for D staging

    float* Dsm = (float*)arena;          // [2][64][65]
    {
        int r0 = strip*16 + (lid >> 2);
        int c0 = (lid & 3)*2;
        #pragma unroll
        for (int nt = 0; nt < 8; nt++) {
            int c = nt*8 + c0;
            Dsm[(dh*64 + r0)*65 + c]       = acc[nt][0];
            Dsm[(dh*64 + r0)*65 + c + 1]   = acc[nt][1];
            Dsm[(dh*64 + r0 + 8)*65 + c]     = acc[nt][2];
            Dsm[(dh*64 + r0 + 8)*65 + c + 1] = acc[nt][3];
        }
    }
    __syncthreads();

    // maxpool(2h x 4w) + bias + relu -> g_a2[b, co, r, pw]
    for (int idx = tid; idx < 800; idx += 256) {
        int co = idx >> 4, pw = idx & 15;
        float mx = -1e30f;
        #pragma unroll
        for (int dhh = 0; dhh < 2; dhh++)
            #pragma unroll
            for (int dw = 0; dw < 4; dw++)
                mx = fmaxf(mx, Dsm[(dhh*64 + pw*4 + dw)*65 + co]);
        g_a2[((b*50 + co)*16 + r)*16 + pw] = fmaxf(mx + b2[co], 0.f);
    }
}

// ---------------------------------------------------------------------------
// K3: combine: out[b] = a2[2b] + mean_{hw}(a2[2b+1]).  grid 800 = 16*50.
// ---------------------------------------------------------------------------
__global__ void k3() {
    const int bc = blockIdx.x;
    const int b = bc / 50, c = bc % 50;
    const int t = threadIdx.x;
    const float* ev = g_a2 + ((2*b)*50 + c)*256;
    const float* od = g_a2 + ((2*b + 1)*50 + c)*256;
    __shared__ float red[256];
    red[t] = od[t];
    __syncthreads();
    for (int s = 128; s > 0; s >>= 1) {
        if (t < s) red[t] += red[t + s];
        __syncthreads();
    }
    float mean = red[0] * (1.f/256.f);
    g_a2c[(b*50 + c)*256 + t] = ev[t] + mean;
}

// ---------------------------------------------------------------------------
// K4: zero-upsample(2,4) + conv3 (50->50, 3x5 circular on 32x64) + relu.
// ---------------------------------------------------------------------------
__global__ void __launch_bounds__(128, 8)
k4(const float* __restrict__ w3, const float* __restrict__ b3) {
    __shared__ float sxd[50][2][16];
    const int b = blockIdx.y, bx = blockIdx.x;
    const int h = bx >> 1, cog = bx & 1;
    const int tid = threadIdx.x;
    const int hodd = h & 1;
    const int pA = hodd ? 1 : 0;
    const int rowA = ((h - pA) & 31) >> 1;
    const int rowB = ((h - 2) & 31) >> 1;
    for (int idx = tid; idx < 1600; idx += 128) {
        int cin = idx >> 5, slot = (idx >> 4) & 1, col = idx & 15;
        int row = slot ? rowB : rowA;
        sxd[cin][slot][col] = g_a2c[((b*50 + cin)*16 + row)*16 + col];
    }
    __syncthreads();

    if (tid < 100) {
        const int co = cog*25 + (tid >> 2), cls = tid & 3;
        float acc[16];
        #pragma unroll
        for (int j = 0; j < 16; j++) acc[j] = 0.f;

        #pragma unroll 2
        for (int cin = 0; cin < 50; cin++) {
            const float* wp = w3 + (co*50 + cin)*15;
            {
                float xr[16];
                #pragma unroll
                for (int jj = 0; jj < 4; jj++) {
                    float4 v = *(const float4*)&sxd[cin][0][jj*4];
                    xr[jj*4+0] = v.x; xr[jj*4+1] = v.y;
                    xr[jj*4+2] = v.z; xr[jj*4+3] = v.w;
                }
                float w0 = __ldg(&wp[pA*5 + cls]);
                #pragma unroll
                for (int j = 0; j < 16; j++) acc[j] += w0 * xr[j];
                if (cls == 0) {
                    float w1 = __ldg(&wp[pA*5 + 4]);
                    #pragma unroll
                    for (int j = 0; j < 16; j++)
                        acc[j] += w1 * xr[(j + 15) & 15];
                }
            }
            if (!hodd) {
                float xr[16];
                #pragma unroll
                for (int jj = 0; jj < 4; jj++) {
                    float4 v = *(const float4*)&sxd[cin][1][jj*4];
                    xr[jj*4+0] = v.x; xr[jj*4+1] = v.y;
                    xr[jj*4+2] = v.z; xr[jj*4+3] = v.w;
                }
                float w0 = __ldg(&wp[10 + cls]);
                #pragma unroll
                for (int j = 0; j < 16; j++) acc[j] += w0 * xr[j];
                if (cls == 0) {
                    float w1 = __ldg(&wp[10 + 4]);
                    #pragma unroll
                    for (int j = 0; j < 16; j++)
                        acc[j] += w1 * xr[(j + 15) & 15];
                }
            }
        }
        float bb = b3[co];
        #pragma unroll
        for (int j = 0; j < 16; j++)
            g_a3[((b*50 + co)*32 + h)*64 + cls + 4*j] =
                fmaxf(acc[j] + bb, 0.f);
    }
}

// ---------------------------------------------------------------------------
// K5: zero-upsample(2,4) + conv4 (50->50, 3x7 circular on 64x256) + relu.
// ---------------------------------------------------------------------------
__global__ void __launch_bounds__(224, 3)
k5(const float* __restrict__ w4, const float* __restrict__ b4) {
    __shared__ float2 sxd[50][2][18];
    const int bp = blockIdx.y, bx = blockIdx.x;
    const int h = bx >> 2, qt = bx & 3;
    const int b0 = 2*bp, b1i = 2*bp + 1;
    const int tid = threadIdx.x;
    const int hodd = h & 1;
    const int pA = hodd ? 1 : 0;
    const int rowA = ((h - pA) & 63) >> 1;
    const int rowB = ((h - 2) & 63) >> 1;
    const float* a3b0 = g_a3 + b0*50*2048;
    const float* a3b1 = g_a3 + b1i*50*2048;
    for (int idx = tid; idx < 50*2*17; idx += 224) {
        int cin = idx / 34, s2 = idx % 34;
        int slot = s2 / 17, k = s2 % 17;
        int m = (qt*16 - 1 + k) & 63;
        int row = slot ? rowB : rowA;
        int off = (cin*32 + row)*64 + m;
        sxd[cin][slot][k] = make_float2(a3b0[off], a3b1[off]);
    }
    __syncthreads();

    if (tid < 200) {
        const int co = tid >> 2, cls = tid & 3;
        u64 acc[16];
        #pragma unroll
        for (int j = 0; j < 16; j++) acc[j] = 0ULL;

        for (int cin = 0; cin < 50; cin++) {
            const float* wp = w4 + (co*50 + cin)*21;
            {
                u64 xr[17];
                #pragma unroll
                for (int jj = 0; jj < 8; jj++) {
                    ulonglong2 v = *(const ulonglong2*)&sxd[cin][0][jj*2];
                    xr[jj*2] = v.x; xr[jj*2+1] = v.y;
                }
                xr[16] = lds2(&sxd[cin][0][16]);
                float w0s = __ldg(&wp[pA*7 + cls]);
                u64 w0 = pk2(w0s, w0s);
                #pragma unroll
                for (int j = 0; j < 16; j++) fma2(acc[j], xr[j+1], w0);
                if (cls < 3) {
                    float w1s = __ldg(&wp[pA*7 + cls + 4]);
                    u64 w1 = pk2(w1s, w1s);
                    #pragma unroll
                    for (int j = 0; j < 16; j++) fma2(acc[j], xr[j], w1);
                }
            }
            if (!hodd) {
                u64 xr[17];
                #pragma unroll
                for (int jj = 0; jj < 8; jj++) {
                    ulonglong2 v = *(const ulonglong2*)&sxd[cin][1][jj*2];
                    xr[jj*2] = v.x; xr[jj*2+1] = v.y;
                }
                xr[16] = lds2(&sxd[cin][1][16]);
                float w0s = __ldg(&wp[14 + cls]);
                u64 w0 = pk2(w0s, w0s);
                #pragma unroll
                for (int j = 0; j < 16; j++) fma2(acc[j], xr[j+1], w0);
                if (cls < 3) {
                    float w1s = __ldg(&wp[14 + cls + 4]);
                    u64 w1 = pk2(w1s, w1s);
                    #pragma unroll
                    for (int j = 0; j < 16; j++) fma2(acc[j], xr[j], w1);
                }
            }
        }
        float bb = b4[co];
        #pragma unroll
        for (int j = 0; j < 16; j++) {
            float2 a = up2(acc[j]);
            int off = (co*64 + h)*256 + cls + 4*(qt*16 + j);
            g_a4[b0 *50*16384 + off] = fmaxf(a.x + bb, 0.f);
            g_a4[b1i*50*16384 + off] = fmaxf(a.y + bb, 0.f);
        }
    }
}

// ---------------------------------------------------------------------------
// K6: conv5 (50->1, 3x7 circular on 64x256) + sigmoid. Scalar.
// ---------------------------------------------------------------------------
__global__ void __launch_bounds__(128, 4)
k6(const float* __restrict__ w5, const float* __restrict__ b5,
   float* __restrict__ out) {
    __shared__ float sxc[5][4][320];
    __shared__ float sw[1050];
    const int b = blockIdx.y, hp = blockIdx.x;
    const int h0 = hp*2;
    const int tid = threadIdx.x;
    const int colg = tid & 63, i = tid >> 6;
    const float* a4b = g_a4 + b*50*16384;
    for (int idx = tid; idx < 1050; idx += 128) sw[idx] = w5[idx];

    float acc[4];
    #pragma unroll
    for (int c = 0; c < 4; c++) acc[c] = 0.f;

    #pragma unroll 1
    for (int cb = 0; cb < 50; cb += 5) {
        __syncthreads();
        for (int idx = tid; idx < 5*4*256; idx += 128) {
            int cl = idx >> 10, rr = (idx >> 8) & 3, m = idx & 255;
            int inrow = (h0 - 2 + rr) & 63;
            sxc[cl][rr][m + (m >> 2)] = a4b[((cb + cl)*64 + inrow)*256 + m];
        }
        __syncthreads();
        #pragma unroll 1
        for (int cl = 0; cl < 5; cl++) {
            float wv[21];
            #pragma unroll
            for (int t = 0; t < 21; t++) wv[t] = sw[(cb + cl)*21 + t];
            #pragma unroll
            for (int dp = 0; dp < 3; dp++) {
                int rr = i + dp;
                int p = 2 - dp;
                float xv[10];
                #pragma unroll
                for (int j = 0; j < 10; j++) {
                    int m = (colg*4 - 6 + j) & 255;
                    xv[j] = sxc[cl][rr][m + (m >> 2)];
                }
                #pragma unroll
                for (int q = 0; q < 7; q++) {
                    float w = wv[p*7 + q];
                    #pragma unroll
                    for (int c = 0; c < 4; c++)
                        acc[c] += w * xv[c + 6 - q];
                }
            }
        }
    }
    float bb = b5[0];
    #pragma unroll
    for (int c = 0; c < 4; c++) {
        float z = acc[c] + bb;
        out[(b*64 + h0 + i)*256 + colg*4 + c] = 1.f / (1.f + expf(-z));
    }
}

// ---------------------------------------------------------------------------
extern "C" void kernel_launch(void* const* d_in, const int* in_sizes, int n_in,
                              void* d_out, int out_size) {
    const float* x  = (const float*)d_in[0];
    const float* w1 = (const float*)d_in[1];
    const float* b1 = (const float*)d_in[2];
    const float* w2 = (const float*)d_in[3];
    const float* b2 = (const float*)d_in[4];
    const float* w3 = (const float*)d_in[5];
    const float* b3 = (const float*)d_in[6];
    const float* w4 = (const float*)d_in[7];
    const float* b4 = (const float*)d_in[8];
    const float* w5 = (const float*)d_in[9];
    const float* b5 = (const float*)d_in[10];
    float* out = (float*)d_out;

    static bool attr_set = false;
    if (!attr_set) {
        cudaFuncSetAttribute(k2m, cudaFuncAttributeMaxDynamicSharedMemorySize,
                             106496);
        attr_set = true;
    }

    k2w<<<21, 256>>>(w2);                       // idx 0
    k1<<<dim3(8, 32), 256>>>(x, w1, b1);        // idx 1
    k1t<<<dim3(32, 32), 256>>>();               // idx 2
    k2m<<<dim3(16, 32), 256, 106496>>>(b2);     // idx 3 <- ncu capture
    k3<<<800, 256>>>();
    k4<<<dim3(64, 16), 128>>>(w3, b3);
    k5<<<dim3(256, 8), 224>>>(w4, b4);
    k6<<<dim3(32, 16), 128>>>(w5, b5, out);
}